// round 1
// baseline (speedup 1.0000x reference)
#include <cuda_runtime.h>
#include <cuda_bf16.h>
#include <math.h>

// GCN: N<=100000 nodes, E<=1280000 edges, dims 18 -> 32 -> 64 -> 2, log_softmax.
// Strategy: build CSR (grouped by dst) per launch, then gather-based aggregation
// (no float atomics). Intermediate feature maps live in __device__ scratch and
// stay L2-resident (12.8MB + 25.6MB << 126MB L2).

#define MAXN 100000
#define MAXE 1280000
#define SCAN_B 512
#define MAX_BLOCKS_SCAN ((MAXN + SCAN_B - 1) / SCAN_B)
#define FULL 0xffffffffu

__device__ int   g_deg[MAXN];
__device__ int   g_ex[MAXN];         // per-block exclusive scan (local)
__device__ int   g_bsum[MAX_BLOCKS_SCAN + 1];
__device__ int   g_rowstart[MAXN + 1];
__device__ int   g_cursor[MAXN];
__device__ int   g_csr[MAXE];
__device__ float g_dinv[MAXN];
__device__ float g_xw1[MAXN * 32];   // x @ W1
__device__ float g_h2w[MAXN * 64];   // relu(agg1+b1) @ W2

// ---------------- CSR build ----------------

__global__ void k_zero(int n) {
    int i = blockIdx.x * blockDim.x + threadIdx.x;
    if (i < n) g_deg[i] = 0;
}

__global__ void k_count(const int* __restrict__ dst, int e) {
    int i = blockIdx.x * blockDim.x + threadIdx.x;
    if (i < e) atomicAdd(&g_deg[dst[i]], 1);
}

__global__ void k_scan_blocks(int n) {
    __shared__ int sh[SCAN_B];
    int t = threadIdx.x;
    int gi = blockIdx.x * SCAN_B + t;
    int v = (gi < n) ? g_deg[gi] : 0;
    sh[t] = v;
    __syncthreads();
    #pragma unroll
    for (int off = 1; off < SCAN_B; off <<= 1) {
        int x = (t >= off) ? sh[t - off] : 0;
        __syncthreads();
        sh[t] += x;
        __syncthreads();
    }
    if (gi < n) g_ex[gi] = sh[t] - v;          // exclusive within block
    if (t == SCAN_B - 1) g_bsum[blockIdx.x] = sh[t];
}

__global__ void k_scan_sums(int nb) {
    if (threadIdx.x == 0 && blockIdx.x == 0) {
        int run = 0;
        for (int b = 0; b < nb; b++) {
            int t = g_bsum[b];
            g_bsum[b] = run;
            run += t;
        }
    }
}

__global__ void k_scan_fix(int n, int e) {
    int i = blockIdx.x * blockDim.x + threadIdx.x;
    if (i < n) {
        int rs = g_ex[i] + g_bsum[i / SCAN_B];
        g_rowstart[i] = rs;
        g_cursor[i]   = rs;
        g_dinv[i]     = rsqrtf((float)(g_deg[i] + 1));   // +1 self loop
    }
    if (i == 0) g_rowstart[n] = e;
}

__global__ void k_scatter(const int* __restrict__ src, const int* __restrict__ dst, int e) {
    int i = blockIdx.x * blockDim.x + threadIdx.x;
    if (i < e) {
        int d = dst[i];
        int p = atomicAdd(&g_cursor[d], 1);
        g_csr[p] = src[i];
    }
}

// ---------------- layer 1 transform: xw1 = x @ W1  (18 -> 32) ----------------

__global__ void k_xw1(const float* __restrict__ x, const float* __restrict__ W1, int n) {
    __shared__ float sW1[18 * 32];
    for (int i = threadIdx.x; i < 18 * 32; i += blockDim.x) sW1[i] = W1[i];
    __syncthreads();
    int lane = threadIdx.x & 31;
    int warp = (blockIdx.x * blockDim.x + threadIdx.x) >> 5;
    int nw   = (gridDim.x * blockDim.x) >> 5;
    for (int i = warp; i < n; i += nw) {
        float xv = (lane < 18) ? x[i * 18 + lane] : 0.f;
        float acc = 0.f;
        #pragma unroll
        for (int k = 0; k < 18; k++) {
            float xk = __shfl_sync(FULL, xv, k);
            acc = fmaf(xk, sW1[k * 32 + lane], acc);
        }
        g_xw1[i * 32 + lane] = acc;
    }
}

// ------- agg1 + relu + transform2:  h2w = relu(aggr(xw1)+b1) @ W2  (32 -> 64) ----

__global__ void __launch_bounds__(256) k_agg1(const float* __restrict__ b1,
                                              const float* __restrict__ W2, int n) {
    __shared__ float sW2[32 * 64];
    __shared__ float sb1[32];
    for (int i = threadIdx.x; i < 32 * 64; i += blockDim.x) sW2[i] = W2[i];
    if (threadIdx.x < 32) sb1[threadIdx.x] = b1[threadIdx.x];
    __syncthreads();
    const float2* sW2v = (const float2*)sW2;

    int lane = threadIdx.x & 31;
    int warp = (blockIdx.x * blockDim.x + threadIdx.x) >> 5;
    int nw   = (gridDim.x * blockDim.x) >> 5;
    for (int i = warp; i < n; i += nw) {
        float di = g_dinv[i];
        float s  = di * g_xw1[i * 32 + lane];      // self loop term
        int e0 = g_rowstart[i], e1 = g_rowstart[i + 1];
        for (int e = e0; e < e1; e++) {
            int j = g_csr[e];
            s = fmaf(g_dinv[j], g_xw1[j * 32 + lane], s);
        }
        float h = fmaxf(fmaf(di, s, sb1[lane]), 0.f);
        float a0 = 0.f, a1 = 0.f;
        #pragma unroll
        for (int l = 0; l < 32; l++) {
            float v  = __shfl_sync(FULL, h, l);
            float2 w = sW2v[l * 32 + lane];        // (W2[l][2*lane], W2[l][2*lane+1])
            a0 = fmaf(v, w.x, a0);
            a1 = fmaf(v, w.y, a1);
        }
        ((float2*)g_h2w)[i * 32 + lane] = make_float2(a0, a1);
    }
}

// ---- agg2 + relu + FC + log_softmax:  out = logsoftmax(relu(aggr(h2w)+b2) @ Wfc + bfc) ----

__global__ void __launch_bounds__(256) k_agg2(const float* __restrict__ b2,
                                              const float* __restrict__ Wfc,
                                              const float* __restrict__ bfc,
                                              float* __restrict__ out, int n) {
    __shared__ float sWfc[128];
    __shared__ float sb2[64];
    __shared__ float sbfc[2];
    if (threadIdx.x < 128) sWfc[threadIdx.x] = Wfc[threadIdx.x];
    if (threadIdx.x < 64)  sb2[threadIdx.x]  = b2[threadIdx.x];
    if (threadIdx.x < 2)   sbfc[threadIdx.x] = bfc[threadIdx.x];
    __syncthreads();

    int lane = threadIdx.x & 31;
    int warp = (blockIdx.x * blockDim.x + threadIdx.x) >> 5;
    int nw   = (gridDim.x * blockDim.x) >> 5;
    for (int i = warp; i < n; i += nw) {
        float di = g_dinv[i];
        float sA = di * g_h2w[i * 64 + lane];
        float sB = di * g_h2w[i * 64 + lane + 32];
        int e0 = g_rowstart[i], e1 = g_rowstart[i + 1];
        for (int e = e0; e < e1; e++) {
            int j = g_csr[e];
            float dj = g_dinv[j];
            sA = fmaf(dj, g_h2w[j * 64 + lane], sA);
            sB = fmaf(dj, g_h2w[j * 64 + lane + 32], sB);
        }
        float hA = fmaxf(fmaf(di, sA, sb2[lane]), 0.f);
        float hB = fmaxf(fmaf(di, sB, sb2[lane + 32]), 0.f);
        float p0 = hA * sWfc[lane * 2]     + hB * sWfc[(lane + 32) * 2];
        float p1 = hA * sWfc[lane * 2 + 1] + hB * sWfc[(lane + 32) * 2 + 1];
        #pragma unroll
        for (int o = 16; o; o >>= 1) {
            p0 += __shfl_xor_sync(FULL, p0, o);
            p1 += __shfl_xor_sync(FULL, p1, o);
        }
        if (lane == 0) {
            float l0 = p0 + sbfc[0];
            float l1 = p1 + sbfc[1];
            float m  = fmaxf(l0, l1);
            float lse = m + logf(expf(l0 - m) + expf(l1 - m));
            ((float2*)out)[i] = make_float2(l0 - lse, l1 - lse);
        }
    }
}

// ---------------- launch ----------------

extern "C" void kernel_launch(void* const* d_in, const int* in_sizes, int n_in,
                              void* d_out, int out_size) {
    const float* x   = (const float*)d_in[0];
    const int*   ei  = (const int*)d_in[1];
    const float* W1  = (const float*)d_in[2];
    const float* b1  = (const float*)d_in[3];
    const float* W2  = (const float*)d_in[4];
    const float* b2  = (const float*)d_in[5];
    const float* Wfc = (const float*)d_in[6];
    const float* bfc = (const float*)d_in[7];
    float* out = (float*)d_out;

    int n = in_sizes[0] / 18;
    int e = in_sizes[1] / 2;
    const int* src = ei;
    const int* dst = ei + e;

    int nb = (n + SCAN_B - 1) / SCAN_B;

    k_zero<<<(n + 255) / 256, 256>>>(n);
    k_count<<<(e + 255) / 256, 256>>>(dst, e);
    k_scan_blocks<<<nb, SCAN_B>>>(n);
    k_scan_sums<<<1, 32>>>(nb);
    k_scan_fix<<<(n + 255) / 256, 256>>>(n, e);
    k_scatter<<<(e + 255) / 256, 256>>>(src, dst, e);

    k_xw1<<<592, 256>>>(x, W1, n);
    k_agg1<<<1184, 256>>>(b1, W2, n);
    k_agg2<<<1184, 256>>>(b2, Wfc, bfc, out, n);
}

// round 2
// speedup vs baseline: 1.2243x; 1.2243x over previous
#include <cuda_runtime.h>
#include <cuda_bf16.h>
#include <math.h>

// GCN: N<=100000 nodes, E<=1280000 edges, dims 18 -> 32 -> 64 -> 2, log_softmax.
// Key algebra: aggregation is linear, so agg(h @ W2) == agg(h) @ W2.
// Both aggregation passes therefore gather only 32-dim (128B/edge) rows.
// Stored rows are pre-scaled by dinv so the edge loop is pure float adds.

#define MAXN 100000
#define MAXE 1280000
#define SCAN_B 512
#define MAX_BLOCKS_SCAN ((MAXN + SCAN_B - 1) / SCAN_B)
#define FULL 0xffffffffu

__device__ int   g_deg[MAXN];
__device__ int   g_ex[MAXN];
__device__ int   g_bsum[MAX_BLOCKS_SCAN + 1];
__device__ int   g_rowstart[MAXN + 1];
__device__ int   g_cursor[MAXN];
__device__ int   g_csr[MAXE];
__device__ float g_dinv[MAXN];
__device__ float g_p [MAXN * 32];   // dinv[i] * (x @ W1)[i]
__device__ float g_hs[MAXN * 32];   // dinv[i] * relu(layer1)[i]

// ---------------- CSR build ----------------

__global__ void k_zero(int n) {
    int i = blockIdx.x * blockDim.x + threadIdx.x;
    if (i < n) g_deg[i] = 0;
}

__global__ void k_count(const int* __restrict__ dst, int e) {
    int i = blockIdx.x * blockDim.x + threadIdx.x;
    if (i < e) atomicAdd(&g_deg[dst[i]], 1);
}

__global__ void k_scan_blocks(int n) {
    __shared__ int sh[SCAN_B];
    int t = threadIdx.x;
    int gi = blockIdx.x * SCAN_B + t;
    int v = (gi < n) ? g_deg[gi] : 0;
    sh[t] = v;
    __syncthreads();
    #pragma unroll
    for (int off = 1; off < SCAN_B; off <<= 1) {
        int x = (t >= off) ? sh[t - off] : 0;
        __syncthreads();
        sh[t] += x;
        __syncthreads();
    }
    if (gi < n) g_ex[gi] = sh[t] - v;
    if (t == SCAN_B - 1) g_bsum[blockIdx.x] = sh[t];
}

// parallel single-block scan of the per-block sums (nb <= 256)
__global__ void k_scan_sums(int nb) {
    __shared__ int sh[256];
    int t = threadIdx.x;
    int v = (t < nb) ? g_bsum[t] : 0;
    sh[t] = v;
    __syncthreads();
    #pragma unroll
    for (int off = 1; off < 256; off <<= 1) {
        int x = (t >= off) ? sh[t - off] : 0;
        __syncthreads();
        sh[t] += x;
        __syncthreads();
    }
    if (t < nb) g_bsum[t] = sh[t] - v;   // exclusive
}

__global__ void k_scan_fix(int n, int e) {
    int i = blockIdx.x * blockDim.x + threadIdx.x;
    if (i < n) {
        int rs = g_ex[i] + g_bsum[i / SCAN_B];
        g_rowstart[i] = rs;
        g_cursor[i]   = rs;
        g_dinv[i]     = rsqrtf((float)(g_deg[i] + 1));   // +1 self loop
    }
    if (i == 0) g_rowstart[n] = e;
}

__global__ void k_scatter(const int* __restrict__ src, const int* __restrict__ dst, int e) {
    int i = blockIdx.x * blockDim.x + threadIdx.x;
    if (i < e) {
        int d = dst[i];
        int p = atomicAdd(&g_cursor[d], 1);
        g_csr[p] = src[i];
    }
}

// ---------------- xw1 pre-scaled:  g_p = dinv * (x @ W1)  (18 -> 32) -------------

__global__ void k_xw1(const float* __restrict__ x, const float* __restrict__ W1, int n) {
    __shared__ float sW1[18 * 32];
    for (int i = threadIdx.x; i < 18 * 32; i += blockDim.x) sW1[i] = W1[i];
    __syncthreads();
    int lane = threadIdx.x & 31;
    int warp = (blockIdx.x * blockDim.x + threadIdx.x) >> 5;
    int nw   = (gridDim.x * blockDim.x) >> 5;
    for (int i = warp; i < n; i += nw) {
        float xv = (lane < 18) ? x[i * 18 + lane] : 0.f;
        float acc = 0.f;
        #pragma unroll
        for (int k = 0; k < 18; k++) {
            float xk = __shfl_sync(FULL, xv, k);
            acc = fmaf(xk, sW1[k * 32 + lane], acc);
        }
        g_p[i * 32 + lane] = g_dinv[i] * acc;
    }
}

// ---- agg1 + relu, store pre-scaled:  g_hs = dinv * relu(di*agg(g_p) + b1) ----

__global__ void __launch_bounds__(256) k_agg1(const float* __restrict__ b1, int n) {
    __shared__ float sb1[32];
    if (threadIdx.x < 32) sb1[threadIdx.x] = b1[threadIdx.x];
    __syncthreads();

    int lane = threadIdx.x & 31;
    int warp = (blockIdx.x * blockDim.x + threadIdx.x) >> 5;
    int nw   = (gridDim.x * blockDim.x) >> 5;
    for (int i = warp; i < n; i += nw) {
        float di = g_dinv[i];
        int e0 = g_rowstart[i];
        int cnt = g_rowstart[i + 1] - e0;
        const int* cp = g_csr + e0;
        float s0 = g_p[i * 32 + lane];    // self-loop term (already di*xw1)
        float s1 = 0.f, s2 = 0.f, s3 = 0.f;
        int k = 0;
        for (; k + 4 <= cnt; k += 4) {
            int j0 = __ldg(cp + k), j1 = __ldg(cp + k + 1);
            int j2 = __ldg(cp + k + 2), j3 = __ldg(cp + k + 3);
            s0 += __ldg(&g_p[j0 * 32 + lane]);
            s1 += __ldg(&g_p[j1 * 32 + lane]);
            s2 += __ldg(&g_p[j2 * 32 + lane]);
            s3 += __ldg(&g_p[j3 * 32 + lane]);
        }
        for (; k < cnt; k++) s0 += __ldg(&g_p[__ldg(cp + k) * 32 + lane]);
        float s = (s0 + s1) + (s2 + s3);
        float h = fmaxf(fmaf(di, s, sb1[lane]), 0.f);
        g_hs[i * 32 + lane] = di * h;
    }
}

// ---- agg2 + W2 + relu + FC + log_softmax (W2 applied AFTER aggregation) ----

__global__ void __launch_bounds__(256) k_agg2(const float* __restrict__ W2,
                                              const float* __restrict__ b2,
                                              const float* __restrict__ Wfc,
                                              const float* __restrict__ bfc,
                                              float* __restrict__ out, int n) {
    __shared__ float sW2[32 * 64];
    __shared__ float sWfc[128];
    __shared__ float sb2[64];
    __shared__ float sbfc[2];
    for (int i = threadIdx.x; i < 32 * 64; i += blockDim.x) sW2[i] = W2[i];
    if (threadIdx.x < 128) sWfc[threadIdx.x] = Wfc[threadIdx.x];
    if (threadIdx.x < 64)  sb2[threadIdx.x]  = b2[threadIdx.x];
    if (threadIdx.x < 2)   sbfc[threadIdx.x] = bfc[threadIdx.x];
    __syncthreads();
    const float2* sW2v = (const float2*)sW2;
    const float2* sb2v = (const float2*)sb2;

    int lane = threadIdx.x & 31;
    int warp = (blockIdx.x * blockDim.x + threadIdx.x) >> 5;
    int nw   = (gridDim.x * blockDim.x) >> 5;
    for (int i = warp; i < n; i += nw) {
        float di = g_dinv[i];
        int e0 = g_rowstart[i];
        int cnt = g_rowstart[i + 1] - e0;
        const int* cp = g_csr + e0;
        float s0 = g_hs[i * 32 + lane];   // self-loop (already di*h)
        float s1 = 0.f, s2 = 0.f, s3 = 0.f;
        int k = 0;
        for (; k + 4 <= cnt; k += 4) {
            int j0 = __ldg(cp + k), j1 = __ldg(cp + k + 1);
            int j2 = __ldg(cp + k + 2), j3 = __ldg(cp + k + 3);
            s0 += __ldg(&g_hs[j0 * 32 + lane]);
            s1 += __ldg(&g_hs[j1 * 32 + lane]);
            s2 += __ldg(&g_hs[j2 * 32 + lane]);
            s3 += __ldg(&g_hs[j3 * 32 + lane]);
        }
        for (; k < cnt; k++) s0 += __ldg(&g_hs[__ldg(cp + k) * 32 + lane]);
        float t = di * ((s0 + s1) + (s2 + s3));   // aggregated 32-dim layer-2 input

        // t @ W2 (32 -> 64), features (2*lane, 2*lane+1) per lane
        float a0 = 0.f, a1 = 0.f;
        #pragma unroll
        for (int l = 0; l < 32; l++) {
            float v  = __shfl_sync(FULL, t, l);
            float2 w = sW2v[l * 32 + lane];
            a0 = fmaf(v, w.x, a0);
            a1 = fmaf(v, w.y, a1);
        }
        float2 bb = sb2v[lane];
        float hA = fmaxf(a0 + bb.x, 0.f);
        float hB = fmaxf(a1 + bb.y, 0.f);
        // logits = h64 @ Wfc (64 -> 2); lane holds features 2*lane, 2*lane+1
        float p0 = hA * sWfc[(2 * lane) * 2]     + hB * sWfc[(2 * lane + 1) * 2];
        float p1 = hA * sWfc[(2 * lane) * 2 + 1] + hB * sWfc[(2 * lane + 1) * 2 + 1];
        #pragma unroll
        for (int o = 16; o; o >>= 1) {
            p0 += __shfl_xor_sync(FULL, p0, o);
            p1 += __shfl_xor_sync(FULL, p1, o);
        }
        if (lane == 0) {
            float l0 = p0 + sbfc[0];
            float l1 = p1 + sbfc[1];
            float m  = fmaxf(l0, l1);
            float lse = m + logf(expf(l0 - m) + expf(l1 - m));
            ((float2*)out)[i] = make_float2(l0 - lse, l1 - lse);
        }
    }
}

// ---------------- launch ----------------

extern "C" void kernel_launch(void* const* d_in, const int* in_sizes, int n_in,
                              void* d_out, int out_size) {
    const float* x   = (const float*)d_in[0];
    const int*   ei  = (const int*)d_in[1];
    const float* W1  = (const float*)d_in[2];
    const float* b1  = (const float*)d_in[3];
    const float* W2  = (const float*)d_in[4];
    const float* b2  = (const float*)d_in[5];
    const float* Wfc = (const float*)d_in[6];
    const float* bfc = (const float*)d_in[7];
    float* out = (float*)d_out;

    int n = in_sizes[0] / 18;
    int e = in_sizes[1] / 2;
    const int* src = ei;
    const int* dst = ei + e;

    int nb = (n + SCAN_B - 1) / SCAN_B;

    k_zero<<<(n + 255) / 256, 256>>>(n);
    k_count<<<(e + 255) / 256, 256>>>(dst, e);
    k_scan_blocks<<<nb, SCAN_B>>>(n);
    k_scan_sums<<<1, 256>>>(nb);
    k_scan_fix<<<(n + 255) / 256, 256>>>(n, e);
    k_scatter<<<(e + 255) / 256, 256>>>(src, dst, e);

    k_xw1<<<592, 256>>>(x, W1, n);
    k_agg1<<<1184, 256>>>(b1, n);
    k_agg2<<<1184, 256>>>(W2, b2, Wfc, bfc, out, n);
}

// round 4
// speedup vs baseline: 1.2648x; 1.0331x over previous
#include <cuda_runtime.h>
#include <cuda_bf16.h>
#include <math.h>

// GCN: N<=100000, E<=1280000, 18 -> 32 -> 64 -> 2, log_softmax.
// agg(h @ W2) == agg(h) @ W2  => both gathers are 32-dim (128B/edge).
// CSR built per launch with block-atomic segment allocation (no prefix-sum
// kernels). 5 kernels + 1 memset total.

#define MAXN 100000
#define MAXE 1280000
#define FULL 0xffffffffu

__device__ int   g_deg[MAXN];
__device__ int   g_total;
__device__ int2  g_rsdeg[MAXN];      // (rowstart, deg)
__device__ int   g_cursor[MAXN];
__device__ int   g_csr[MAXE];
__device__ float g_dinv[MAXN];
__device__ float g_p [MAXN * 32];    // dinv[i] * (x @ W1)[i]
__device__ float g_hs[MAXN * 32];    // dinv[i] * relu(layer1)[i]

// ---------------- degree count ----------------

__global__ void k_count(const int* __restrict__ dst, int e) {
    int i = blockIdx.x * blockDim.x + threadIdx.x;
    if (i == 0) g_total = 0;
    if (i < e) atomicAdd(&g_deg[dst[i]], 1);
}

// ------- alloc (block-atomic segment allocation) + dinv + xw1 pre-scaled -------
// phase 1: thread-per-node: block scan of degrees, one atomicAdd per block,
//          write rowstart/cursor/dinv.
// phase 2: warp-per-node: g_p[i] = dinv[i] * (x[i] @ W1).

__global__ void __launch_bounds__(256) k_alloc_xw1(const float* __restrict__ x,
                                                   const float* __restrict__ W1, int n) {
    __shared__ float sW1[18 * 32];
    __shared__ int   ssc[256];
    __shared__ float sdinv[256];
    __shared__ int   sbase;
    for (int i = threadIdx.x; i < 18 * 32; i += blockDim.x) sW1[i] = W1[i];

    int t = threadIdx.x;
    int i = blockIdx.x * 256 + t;
    int d = (i < n) ? g_deg[i] : 0;
    ssc[t] = d;
    __syncthreads();
    #pragma unroll
    for (int off = 1; off < 256; off <<= 1) {
        int v = (t >= off) ? ssc[t - off] : 0;
        __syncthreads();
        ssc[t] += v;
        __syncthreads();
    }
    if (t == 255) sbase = atomicAdd(&g_total, ssc[255]);
    __syncthreads();
    float di = rsqrtf((float)(d + 1));
    if (i < n) {
        int rs = sbase + ssc[t] - d;     // exclusive within block + block base
        g_rsdeg[i]  = make_int2(rs, d);
        g_cursor[i] = rs;
        g_dinv[i]   = di;
        sdinv[t]    = di;
    }
    __syncthreads();

    // phase 2: warp w covers nodes [blk*256 + w*32, +32)
    int lane = t & 31;
    int w    = t >> 5;
    int base = blockIdx.x * 256 + w * 32;
    #pragma unroll 1
    for (int q = 0; q < 32; q++) {
        int node = base + q;
        if (node >= n) break;
        float xv = (lane < 18) ? __ldg(&x[node * 18 + lane]) : 0.f;
        float acc = 0.f;
        #pragma unroll
        for (int k = 0; k < 18; k++) {
            float xk = __shfl_sync(FULL, xv, k);
            acc = fmaf(xk, sW1[k * 32 + lane], acc);
        }
        g_p[node * 32 + lane] = sdinv[w * 32 + q] * acc;
    }
}

// ---------------- scatter edges into CSR ----------------

__global__ void k_scatter(const int* __restrict__ src, const int* __restrict__ dst, int e) {
    int i = blockIdx.x * blockDim.x + threadIdx.x;
    if (i < e) {
        int d = dst[i];
        int p = atomicAdd(&g_cursor[d], 1);
        g_csr[p] = src[i];
    }
}

// ---- agg1 + relu, store pre-scaled:  g_hs = dinv * relu(di*agg(g_p) + b1) ----

__global__ void __launch_bounds__(256) k_agg1(const float* __restrict__ b1, int n) {
    __shared__ float sb1[32];
    if (threadIdx.x < 32) sb1[threadIdx.x] = b1[threadIdx.x];
    __syncthreads();

    int lane = threadIdx.x & 31;
    int warp = (blockIdx.x * blockDim.x + threadIdx.x) >> 5;
    int nw   = (gridDim.x * blockDim.x) >> 5;
    for (int i = warp; i < n; i += nw) {
        float di = g_dinv[i];
        int2 rd = g_rsdeg[i];
        const int* cp = g_csr + rd.x;
        int cnt = rd.y;
        float s0 = g_p[i * 32 + lane];    // self-loop (already di*xw1)
        float s1 = 0.f, s2 = 0.f, s3 = 0.f;
        int k = 0;
        for (; k + 4 <= cnt; k += 4) {
            int j0 = __ldg(cp + k), j1 = __ldg(cp + k + 1);
            int j2 = __ldg(cp + k + 2), j3 = __ldg(cp + k + 3);
            s0 += __ldg(&g_p[j0 * 32 + lane]);
            s1 += __ldg(&g_p[j1 * 32 + lane]);
            s2 += __ldg(&g_p[j2 * 32 + lane]);
            s3 += __ldg(&g_p[j3 * 32 + lane]);
        }
        for (; k < cnt; k++) s0 += __ldg(&g_p[__ldg(cp + k) * 32 + lane]);
        float s = (s0 + s1) + (s2 + s3);
        float h = fmaxf(fmaf(di, s, sb1[lane]), 0.f);
        g_hs[i * 32 + lane] = di * h;
    }
}

// ---- agg2 + W2 + relu + FC + log_softmax (W2 applied AFTER aggregation) ----

__global__ void __launch_bounds__(256) k_agg2(const float* __restrict__ W2,
                                              const float* __restrict__ b2,
                                              const float* __restrict__ Wfc,
                                              const float* __restrict__ bfc,
                                              float* __restrict__ out, int n) {
    __shared__ float sW2[32 * 64];
    __shared__ float sWfc[128];
    __shared__ float sb2[64];
    __shared__ float sbfc[2];
    for (int i = threadIdx.x; i < 32 * 64; i += blockDim.x) sW2[i] = W2[i];
    if (threadIdx.x < 128) sWfc[threadIdx.x] = Wfc[threadIdx.x];
    if (threadIdx.x < 64)  sb2[threadIdx.x]  = b2[threadIdx.x];
    if (threadIdx.x < 2)   sbfc[threadIdx.x] = bfc[threadIdx.x];
    __syncthreads();
    const float2* sW2v = (const float2*)sW2;
    const float2* sb2v = (const float2*)sb2;

    int lane = threadIdx.x & 31;
    int warp = (blockIdx.x * blockDim.x + threadIdx.x) >> 5;
    int nw   = (gridDim.x * blockDim.x) >> 5;
    for (int i = warp; i < n; i += nw) {
        float di = g_dinv[i];
        int2 rd = g_rsdeg[i];
        const int* cp = g_csr + rd.x;
        int cnt = rd.y;
        float s0 = g_hs[i * 32 + lane];   // self-loop (already di*h)
        float s1 = 0.f, s2 = 0.f, s3 = 0.f;
        int k = 0;
        for (; k + 4 <= cnt; k += 4) {
            int j0 = __ldg(cp + k), j1 = __ldg(cp + k + 1);
            int j2 = __ldg(cp + k + 2), j3 = __ldg(cp + k + 3);
            s0 += __ldg(&g_hs[j0 * 32 + lane]);
            s1 += __ldg(&g_hs[j1 * 32 + lane]);
            s2 += __ldg(&g_hs[j2 * 32 + lane]);
            s3 += __ldg(&g_hs[j3 * 32 + lane]);
        }
        for (; k < cnt; k++) s0 += __ldg(&g_hs[__ldg(cp + k) * 32 + lane]);
        float tt = di * ((s0 + s1) + (s2 + s3));   // aggregated 32-dim input

        // tt @ W2 (32 -> 64): lane holds output features (2*lane, 2*lane+1)
        float a0 = 0.f, a1 = 0.f;
        #pragma unroll
        for (int l = 0; l < 32; l++) {
            float v  = __shfl_sync(FULL, tt, l);
            float2 w = sW2v[l * 32 + lane];
            a0 = fmaf(v, w.x, a0);
            a1 = fmaf(v, w.y, a1);
        }
        float2 bb = sb2v[lane];
        float hA = fmaxf(a0 + bb.x, 0.f);
        float hB = fmaxf(a1 + bb.y, 0.f);
        float p0 = hA * sWfc[(2 * lane) * 2]     + hB * sWfc[(2 * lane + 1) * 2];
        float p1 = hA * sWfc[(2 * lane) * 2 + 1] + hB * sWfc[(2 * lane + 1) * 2 + 1];
        #pragma unroll
        for (int o = 16; o; o >>= 1) {
            p0 += __shfl_xor_sync(FULL, p0, o);
            p1 += __shfl_xor_sync(FULL, p1, o);
        }
        if (lane == 0) {
            float l0 = p0 + sbfc[0];
            float l1 = p1 + sbfc[1];
            float m  = fmaxf(l0, l1);
            float lse = m + logf(expf(l0 - m) + expf(l1 - m));
            ((float2*)out)[i] = make_float2(l0 - lse, l1 - lse);
        }
    }
}

// ---------------- launch ----------------

extern "C" void kernel_launch(void* const* d_in, const int* in_sizes, int n_in,
                              void* d_out, int out_size) {
    const float* x   = (const float*)d_in[0];
    const int*   ei  = (const int*)d_in[1];
    const float* W1  = (const float*)d_in[2];
    const float* b1  = (const float*)d_in[3];
    const float* W2  = (const float*)d_in[4];
    const float* b2  = (const float*)d_in[5];
    const float* Wfc = (const float*)d_in[6];
    const float* bfc = (const float*)d_in[7];
    float* out = (float*)d_out;

    int n = in_sizes[0] / 18;
    int e = in_sizes[1] / 2;
    const int* src = ei;
    const int* dst = ei + e;

    void* degp = nullptr;
    cudaGetSymbolAddress(&degp, g_deg);
    cudaMemsetAsync(degp, 0, n * sizeof(int));

    k_count<<<(e + 255) / 256, 256>>>(dst, e);
    k_alloc_xw1<<<(n + 255) / 256, 256>>>(x, W1, n);
    k_scatter<<<(e + 255) / 256, 256>>>(src, dst, e);
    k_agg1<<<1184, 256>>>(b1, n);
    k_agg2<<<1184, 256>>>(W2, b2, Wfc, bfc, out, n);
}